// round 1
// baseline (speedup 1.0000x reference)
#include <cuda_runtime.h>

// ---------------------------------------------------------------------------
// EBMAttention: out = softmax(-(q @ (k@W)^T)) @ v, with Linear projections.
// B=8, S=2048, E=1024, H=1. Outputs: out [B,S,E] then attn [B,1,S,S], fp32.
//
// Pipeline:
//   1. b2 = bk @ energy_W                      (tiny)
//   2. W2 = Wk^T @ energy_W                    (2 GFLOP)
//   3. q  = query @ Wq^T + bq                  (34 GFLOP)
//   4. kt = key @ W2 + b2                      (34 GFLOP)  [fused k-proj + k@W]
//   5. v  = value @ Wv^T + bv                  (34 GFLOP)
//   6. s  = -(q @ kt^T)  (masked)  -> attn buf (69 GFLOP)
//   7. row softmax in-place + sparse (j,w) list (attn is ~one-hot)
//   8. out[row] = sum_t w_t * v[j_t]           (sparse gather, ~0 FLOP)
// ---------------------------------------------------------------------------

#define EDIM 1024
#define NBATCH 8
#define SEQ 2048
#define MTOT (NBATCH * SEQ)   // 16384
#define CAP 64

static __device__ float g_q [(size_t)MTOT * EDIM];
static __device__ float g_kt[(size_t)MTOT * EDIM];
static __device__ float g_v [(size_t)MTOT * EDIM];
static __device__ float g_W2[(size_t)EDIM * EDIM];
static __device__ float g_b2[EDIM];
static __device__ int   g_sj[(size_t)MTOT * CAP];
static __device__ float g_sw[(size_t)MTOT * CAP];
static __device__ int   g_cnt[MTOT];

// ---------------------------------------------------------------------------
// Unified 128x128x16 tiled fp32 GEMM, 256 threads, 8x8 per thread.
// AMODE/BMODE: 0 = row-major [rows, K] (transpose into smem),
//              1 = k-major   [K, cols] (direct copy into smem).
// EPI: 0 = C = acc + bias   (bias may be null)
//      1 = C = mask ? -acc : +1e9   (energy epilogue, N == SEQ)
// ---------------------------------------------------------------------------
template <int AMODE, int BMODE, int EPI>
__global__ __launch_bounds__(256)
void gemm_kernel(const float* __restrict__ A, const float* __restrict__ B,
                 const float* __restrict__ bias, const int* __restrict__ maskp,
                 float* __restrict__ C,
                 int M, int N, int K,
                 long long aBatch, long long bBatch, long long cBatch)
{
    __shared__ __align__(16) float As[16][132];
    __shared__ __align__(16) float Bs[16][132];

    const int tid = threadIdx.x;
    const int tx = tid & 15;
    const int ty = tid >> 4;
    const int m0 = blockIdx.y * 128;
    const int n0 = blockIdx.x * 128;
    const long long bz = blockIdx.z;

    A += bz * aBatch;
    B += bz * bBatch;
    C += bz * cBatch;

    float acc[8][8];
#pragma unroll
    for (int i = 0; i < 8; ++i)
#pragma unroll
        for (int j = 0; j < 8; ++j) acc[i][j] = 0.f;

    // mode0 loader coords: 64 rows per pass x 16 k-cols (float4)
    const int r_m0  = tid >> 2;          // 0..63
    const int c4_m0 = (tid & 3) * 4;     // 0,4,8,12
    // mode1 loader coords: 16 k-rows x 128 cols (2x float4)
    const int kr_m1 = tid >> 4;          // 0..15
    const int c8_m1 = (tid & 15) * 8;    // 0..120

    for (int kb = 0; kb < K; kb += 16) {
        // ---- load A tile -> As[k][m] ----
        if (AMODE == 0) {
            float4 v0 = *(const float4*)(A + (long long)(m0 + r_m0) * K + kb + c4_m0);
            float4 v1 = *(const float4*)(A + (long long)(m0 + 64 + r_m0) * K + kb + c4_m0);
            As[c4_m0 + 0][r_m0] = v0.x; As[c4_m0 + 1][r_m0] = v0.y;
            As[c4_m0 + 2][r_m0] = v0.z; As[c4_m0 + 3][r_m0] = v0.w;
            As[c4_m0 + 0][64 + r_m0] = v1.x; As[c4_m0 + 1][64 + r_m0] = v1.y;
            As[c4_m0 + 2][64 + r_m0] = v1.z; As[c4_m0 + 3][64 + r_m0] = v1.w;
        } else {
            float4 v0 = *(const float4*)(A + (long long)(kb + kr_m1) * M + m0 + c8_m1);
            float4 v1 = *(const float4*)(A + (long long)(kb + kr_m1) * M + m0 + c8_m1 + 4);
            *(float4*)&As[kr_m1][c8_m1]     = v0;
            *(float4*)&As[kr_m1][c8_m1 + 4] = v1;
        }
        // ---- load B tile -> Bs[k][n] ----
        if (BMODE == 0) {
            float4 v0 = *(const float4*)(B + (long long)(n0 + r_m0) * K + kb + c4_m0);
            float4 v1 = *(const float4*)(B + (long long)(n0 + 64 + r_m0) * K + kb + c4_m0);
            Bs[c4_m0 + 0][r_m0] = v0.x; Bs[c4_m0 + 1][r_m0] = v0.y;
            Bs[c4_m0 + 2][r_m0] = v0.z; Bs[c4_m0 + 3][r_m0] = v0.w;
            Bs[c4_m0 + 0][64 + r_m0] = v1.x; Bs[c4_m0 + 1][64 + r_m0] = v1.y;
            Bs[c4_m0 + 2][64 + r_m0] = v1.z; Bs[c4_m0 + 3][64 + r_m0] = v1.w;
        } else {
            float4 v0 = *(const float4*)(B + (long long)(kb + kr_m1) * N + n0 + c8_m1);
            float4 v1 = *(const float4*)(B + (long long)(kb + kr_m1) * N + n0 + c8_m1 + 4);
            *(float4*)&Bs[kr_m1][c8_m1]     = v0;
            *(float4*)&Bs[kr_m1][c8_m1 + 4] = v1;
        }
        __syncthreads();

#pragma unroll
        for (int k = 0; k < 16; ++k) {
            float4 a0 = *(const float4*)&As[k][ty * 4];
            float4 a1 = *(const float4*)&As[k][ty * 4 + 64];
            float4 b0 = *(const float4*)&Bs[k][tx * 4];
            float4 b1 = *(const float4*)&Bs[k][tx * 4 + 64];
            float a[8] = {a0.x, a0.y, a0.z, a0.w, a1.x, a1.y, a1.z, a1.w};
            float b[8] = {b0.x, b0.y, b0.z, b0.w, b1.x, b1.y, b1.z, b1.w};
#pragma unroll
            for (int i = 0; i < 8; ++i)
#pragma unroll
                for (int j = 0; j < 8; ++j)
                    acc[i][j] = fmaf(a[i], b[j], acc[i][j]);
        }
        __syncthreads();
    }

    // ---- epilogue ----
#pragma unroll
    for (int i = 0; i < 8; ++i) {
        const int rr = m0 + ((i < 4) ? (ty * 4 + i) : (ty * 4 + i + 60));
#pragma unroll
        for (int jj = 0; jj < 2; ++jj) {
            const int cc = n0 + ((jj == 0) ? (tx * 4) : (tx * 4 + 64));
            float4 o;
            if (EPI == 0) {
                float4 bb = make_float4(0.f, 0.f, 0.f, 0.f);
                if (bias) bb = *(const float4*)(bias + cc);
                o.x = acc[i][jj * 4 + 0] + bb.x;
                o.y = acc[i][jj * 4 + 1] + bb.y;
                o.z = acc[i][jj * 4 + 2] + bb.z;
                o.w = acc[i][jj * 4 + 3] + bb.w;
            } else {
                // s = -energy; masked positions: energy=-1e9 -> s=+1e9
                const int4 mk = *(const int4*)(maskp + (long long)rr * SEQ + cc);
                o.x = (mk.x == 0) ? 1e9f : -acc[i][jj * 4 + 0];
                o.y = (mk.y == 0) ? 1e9f : -acc[i][jj * 4 + 1];
                o.z = (mk.z == 0) ? 1e9f : -acc[i][jj * 4 + 2];
                o.w = (mk.w == 0) ? 1e9f : -acc[i][jj * 4 + 3];
            }
            *(float4*)(C + (long long)rr * N + cc) = o;
        }
    }
}

// b2[n] = sum_c bk[c] * W[c,n]
__global__ void bias2_kernel(const float* __restrict__ bk,
                             const float* __restrict__ W,
                             float* __restrict__ b2)
{
    const int n = blockIdx.x * blockDim.x + threadIdx.x;
    float acc = 0.f;
    for (int c = 0; c < EDIM; ++c)
        acc = fmaf(bk[c], W[(long long)c * EDIM + n], acc);
    b2[n] = acc;
}

// Row softmax in place + sparse significant-weight list.
__global__ __launch_bounds__(256)
void softmax_kernel(float* __restrict__ attn, int* __restrict__ cnt,
                    int* __restrict__ sj, float* __restrict__ sw)
{
    const int row = blockIdx.x;
    float* p = attn + (long long)row * SEQ;
    const int t = threadIdx.x;
    const int lane = t & 31;
    const int w = t >> 5;

    __shared__ float red[8];
    __shared__ int scnt;

    float4 x0 = *(const float4*)(p + t * 4);
    float4 x1 = *(const float4*)(p + 1024 + t * 4);
    float xs[8] = {x0.x, x0.y, x0.z, x0.w, x1.x, x1.y, x1.z, x1.w};

    float m = xs[0];
#pragma unroll
    for (int i = 1; i < 8; ++i) m = fmaxf(m, xs[i]);
#pragma unroll
    for (int off = 16; off > 0; off >>= 1)
        m = fmaxf(m, __shfl_xor_sync(0xFFFFFFFFu, m, off));
    if (lane == 0) red[w] = m;
    __syncthreads();
    if (t == 0) {
        float mm = red[0];
#pragma unroll
        for (int i = 1; i < 8; ++i) mm = fmaxf(mm, red[i]);
        red[0] = mm;
        scnt = 0;
    }
    __syncthreads();
    m = red[0];
    __syncthreads();   // everyone has read red[0] before it is reused

    float s = 0.f;
#pragma unroll
    for (int i = 0; i < 8; ++i) { xs[i] = expf(xs[i] - m); s += xs[i]; }
#pragma unroll
    for (int off = 16; off > 0; off >>= 1)
        s += __shfl_xor_sync(0xFFFFFFFFu, s, off);
    if (lane == 0) red[w] = s;
    __syncthreads();
    if (t == 0) {
        float ss = 0.f;
#pragma unroll
        for (int i = 0; i < 8; ++i) ss += red[i];
        red[0] = ss;
    }
    __syncthreads();
    const float inv = 1.f / red[0];

#pragma unroll
    for (int i = 0; i < 8; ++i) xs[i] *= inv;

    x0 = make_float4(xs[0], xs[1], xs[2], xs[3]);
    x1 = make_float4(xs[4], xs[5], xs[6], xs[7]);
    *(float4*)(p + t * 4)        = x0;
    *(float4*)(p + 1024 + t * 4) = x1;

#pragma unroll
    for (int i = 0; i < 8; ++i) {
        if (xs[i] > 1e-10f) {
            const int col = (i < 4) ? (t * 4 + i) : (1024 + t * 4 + (i - 4));
            const int pos = atomicAdd(&scnt, 1);
            if (pos < CAP) {
                sj[(long long)row * CAP + pos] = col;
                sw[(long long)row * CAP + pos] = xs[i];
            }
        }
    }
    __syncthreads();
    if (t == 0) cnt[row] = (scnt <= CAP) ? scnt : -1;
}

// out[row,:] = sum over significant weights w_t * v[b, j_t, :]
__global__ __launch_bounds__(256)
void av_kernel(const float* __restrict__ attn, const float* __restrict__ v,
               const int* __restrict__ cnt, const int* __restrict__ sj,
               const float* __restrict__ sw, float* __restrict__ out)
{
    const int row = blockIdx.x;           // 0..MTOT-1
    const int b = row >> 11;              // row / SEQ
    const int t = threadIdx.x;
    const float* vb = v + (long long)b * SEQ * EDIM;

    float4 acc = make_float4(0.f, 0.f, 0.f, 0.f);
    const int c = cnt[row];
    if (c >= 0) {
        for (int it = 0; it < c; ++it) {
            const int j = sj[(long long)row * CAP + it];
            const float wv = sw[(long long)row * CAP + it];
            const float4 vv = *(const float4*)(vb + (long long)j * EDIM + t * 4);
            acc.x = fmaf(wv, vv.x, acc.x);
            acc.y = fmaf(wv, vv.y, acc.y);
            acc.z = fmaf(wv, vv.z, acc.z);
            acc.w = fmaf(wv, vv.w, acc.w);
        }
    } else {
        // dense fallback (rare: > CAP significant weights)
        const float* arow = attn + (long long)row * SEQ;
        for (int j = 0; j < SEQ; ++j) {
            const float wv = arow[j];
            if (wv != 0.f) {
                const float4 vv = *(const float4*)(vb + (long long)j * EDIM + t * 4);
                acc.x = fmaf(wv, vv.x, acc.x);
                acc.y = fmaf(wv, vv.y, acc.y);
                acc.z = fmaf(wv, vv.z, acc.z);
                acc.w = fmaf(wv, vv.w, acc.w);
            }
        }
    }
    *(float4*)(out + (long long)row * EDIM + t * 4) = acc;
}

extern "C" void kernel_launch(void* const* d_in, const int* in_sizes, int n_in,
                              void* d_out, int out_size)
{
    const float* query = (const float*)d_in[0];
    const float* key_  = (const float*)d_in[1];
    const float* value = (const float*)d_in[2];
    const int*   mask  = (const int*)  d_in[3];
    const float* Wq    = (const float*)d_in[4];
    const float* bq    = (const float*)d_in[5];
    const float* Wk    = (const float*)d_in[6];
    const float* bk    = (const float*)d_in[7];
    const float* Wv    = (const float*)d_in[8];
    const float* bv    = (const float*)d_in[9];
    const float* eW    = (const float*)d_in[10];

    float* out  = (float*)d_out;
    float* attn = out + (size_t)MTOT * EDIM;

    void* p;
    cudaGetSymbolAddress(&p, g_q);   float* pq  = (float*)p;
    cudaGetSymbolAddress(&p, g_kt);  float* pkt = (float*)p;
    cudaGetSymbolAddress(&p, g_v);   float* pv  = (float*)p;
    cudaGetSymbolAddress(&p, g_W2);  float* pW2 = (float*)p;
    cudaGetSymbolAddress(&p, g_b2);  float* pb2 = (float*)p;
    cudaGetSymbolAddress(&p, g_sj);  int*   psj = (int*)p;
    cudaGetSymbolAddress(&p, g_sw);  float* psw = (float*)p;
    cudaGetSymbolAddress(&p, g_cnt); int*   pcnt = (int*)p;

    // 1. b2 = bk @ eW
    bias2_kernel<<<EDIM / 256, 256>>>(bk, eW, pb2);

    // 2. W2 = Wk^T @ eW   (both k-major)
    gemm_kernel<1, 1, 0><<<dim3(8, 8, 1), 256>>>(
        Wk, eW, nullptr, nullptr, pW2, EDIM, EDIM, EDIM, 0, 0, 0);

    // 3. q = query @ Wq^T + bq
    gemm_kernel<0, 0, 0><<<dim3(8, 128, 1), 256>>>(
        query, Wq, bq, nullptr, pq, MTOT, EDIM, EDIM, 0, 0, 0);

    // 4. kt = key @ W2 + b2
    gemm_kernel<0, 1, 0><<<dim3(8, 128, 1), 256>>>(
        key_, pW2, pb2, nullptr, pkt, MTOT, EDIM, EDIM, 0, 0, 0);

    // 5. v = value @ Wv^T + bv
    gemm_kernel<0, 0, 0><<<dim3(8, 128, 1), 256>>>(
        value, Wv, bv, nullptr, pv, MTOT, EDIM, EDIM, 0, 0, 0);

    // 6. s = -(q @ kt^T), masked -> attn buffer (batched over 8)
    gemm_kernel<0, 0, 1><<<dim3(16, 16, NBATCH), 256>>>(
        pq, pkt, nullptr, mask, attn, SEQ, SEQ, EDIM,
        (long long)SEQ * EDIM, (long long)SEQ * EDIM, (long long)SEQ * SEQ);

    // 7. softmax in place + sparse list
    softmax_kernel<<<MTOT, 256>>>(attn, pcnt, psj, psw);

    // 8. out = sparse attn @ v
    av_kernel<<<MTOT, 256>>>(attn, pv, pcnt, psj, psw, out);
}